// round 15
// baseline (speedup 1.0000x reference)
#include <cuda_runtime.h>
#include <math.h>

#define N_  10000
#define P_  20000
#define EPSc 1e-8f

// ---------------- scratch (device globals, no allocation) ----------------
__device__ __align__(16) float g_e  [P_*32];           // exp(pool logits)
__device__ __align__(16) float g_eq [P_*4];            // qs . ws_q per head
__device__ __align__(16) float g_qh [(size_t)P_*96];   // qh [p][h][d][j]
__device__ __align__(16) float g_num[2*32*176];        // pooled numerators [c][r][s(128)|v(48)]
__device__ __align__(16) float g_Z  [64];              // pooled softmax denominators [c][r]
__device__ __align__(16) float g_ek [64*4];            // ks . ws_k   [rc][h]
__device__ __align__(16) float g_kh [64*96];           // kh [rc][h][d][j]
__device__ __align__(16) float g_vs [64*128];          // silu(so_v)  [rc][128]
__device__ __align__(16) float g_vv [64*48];           // gated vv    [rc][i*3+d]

__device__ __forceinline__ float sigm(float x){ return 1.f/(1.f+__expf(-x)); }

// ---------------- K0: zero accumulators ----------------
__global__ void k_init(){
    int i = blockIdx.x*blockDim.x + threadIdx.x;
    const int tot = 2*32*176 + 64;
    for (; i < tot; i += gridDim.x*blockDim.x){
        if (i < 2*32*176) g_num[i] = 0.f;
        else              g_Z[i - 2*32*176] = 0.f;
    }
}

// ---------------- K1: per-row q-GVP + pooling logits ----------------
// 32 rows/block, 256 threads.
__global__ __launch_bounds__(256) void k_main(
    const float* __restrict__ s, const float* __restrict__ v,
    const float* __restrict__ wp_wh, const float* __restrict__ wp_ws_w, const float* __restrict__ wp_ws_b,
    const float* __restrict__ q_wh,  const float* __restrict__ q_ws_w,  const float* __restrict__ q_ws_b,
    const float* __restrict__ q_wv,  const float* __restrict__ q_wsv_w, const float* __restrict__ q_wsv_b,
    const float* __restrict__ attn_wh, const float* __restrict__ attn_ws_w)
{
    __shared__ __align__(16) float sh_x [32*164];  // s(0..127)->later sigmoid(so); vn_q(128..143); vn_p(144..159)
    __shared__ __align__(16) float sh_v [32*49];   // raw v, later qv[i*3+d]
    __shared__ __align__(16) float sh_vh[32*49];   // vh_q [d*16+i]
    __shared__ float sh_wsv[2048];
    __shared__ float sh_wv[256], sh_qwh[256], sh_pwh[256];
    __shared__ float sh_whq[64], sh_wsvb[16];

    const int tid = threadIdx.x;
    const int pr0 = blockIdx.x * 32;

    for (int i = tid; i < 2048; i += 256) sh_wsv[i] = q_wsv_w[i];
    sh_wv[tid]  = q_wv[tid];
    sh_qwh[tid] = q_wh[tid];
    sh_pwh[tid] = wp_wh[tid];
    if (tid < 64) sh_whq[tid]  = attn_wh[tid];
    if (tid < 16) sh_wsvb[tid] = q_wsv_b[tid];

    {   // stage s rows (float4)
        const float4* s4 = (const float4*)(s + (size_t)pr0*128);
        #pragma unroll
        for (int it = 0; it < 4; it++){
            int idx = tid + it*256;                // 0..1023 float4s
            float4 val = __ldg(&s4[idx]);
            int row = idx >> 5, c4 = idx & 31;
            *(float4*)&sh_x[row*164 + c4*4] = val;
        }
        // stage v rows
        const float* vsrc = v + (size_t)pr0*48;
        #pragma unroll
        for (int it = 0; it < 6; it++){
            int idx = tid + it*256;                // 0..1535
            sh_v[(idx/48)*49 + idx%48] = __ldg(vsrc + idx);
        }
    }
    __syncthreads();

    // ---- phase A: vh (q & pool) + norms. 8 threads/row, thread handles 2 i's.
    {
        const int row = tid >> 3, g = tid & 7;
        #pragma unroll
        for (int ii = 0; ii < 2; ii++){
            int i = g*2 + ii;
            float aq0=0,aq1=0,aq2=0, ap0=0,ap1=0,ap2=0;
            #pragma unroll
            for (int k = 0; k < 16; k++){
                float wq = sh_qwh[k*16+i], wp = sh_pwh[k*16+i];
                float v0 = sh_v[row*49 + k*3+0];
                float v1 = sh_v[row*49 + k*3+1];
                float v2 = sh_v[row*49 + k*3+2];
                aq0 = fmaf(v0,wq,aq0); aq1 = fmaf(v1,wq,aq1); aq2 = fmaf(v2,wq,aq2);
                ap0 = fmaf(v0,wp,ap0); ap1 = fmaf(v1,wp,ap1); ap2 = fmaf(v2,wp,ap2);
            }
            sh_vh[row*49 +  0 + i] = aq0;
            sh_vh[row*49 + 16 + i] = aq1;
            sh_vh[row*49 + 32 + i] = aq2;
            sh_x[row*164 + 128 + i] = sqrtf(fmaxf(aq0*aq0+aq1*aq1+aq2*aq2, EPSc));
            sh_x[row*164 + 144 + i] = sqrtf(fmaxf(ap0*ap0+ap1*ap1+ap2*ap2, EPSc));
        }
    }
    __syncthreads();

    // ---- phase B: so (144x128) + pool logits (144x32). warp: 4 rows; lane: 4 so-cols + 1 pw-col.
    {
        const int w = tid >> 5, L = tid & 31, r0 = w*4;
        float acc[4][4], accp[4];
        #pragma unroll
        for (int r = 0; r < 4; r++){ accp[r] = 0.f;
            #pragma unroll
            for (int j = 0; j < 4; j++) acc[r][j] = 0.f; }
        const float4* Wq4 = (const float4*)q_ws_w;
        for (int k = 0; k < 128; k += 4){
            float4 xr[4];
            #pragma unroll
            for (int r = 0; r < 4; r++) xr[r] = *(const float4*)&sh_x[(r0+r)*164 + k];
            #pragma unroll
            for (int kk = 0; kk < 4; kk++){
                float4 wq = __ldg(&Wq4[(k+kk)*32 + L]);
                float  wp = __ldg(&wp_ws_w[(k+kk)*32 + L]);
                #pragma unroll
                for (int r = 0; r < 4; r++){
                    float xv = (kk==0)?xr[r].x:(kk==1)?xr[r].y:(kk==2)?xr[r].z:xr[r].w;
                    acc[r][0] = fmaf(xv, wq.x, acc[r][0]);
                    acc[r][1] = fmaf(xv, wq.y, acc[r][1]);
                    acc[r][2] = fmaf(xv, wq.z, acc[r][2]);
                    acc[r][3] = fmaf(xv, wq.w, acc[r][3]);
                    accp[r]   = fmaf(xv, wp,   accp[r]);
                }
            }
        }
        #pragma unroll
        for (int k = 128; k < 144; k++){
            float4 wq = __ldg(&Wq4[k*32 + L]);
            float  wp = __ldg(&wp_ws_w[k*32 + L]);
            #pragma unroll
            for (int r = 0; r < 4; r++){
                float xq = sh_x[(r0+r)*164 + k];        // vn_q
                float xp = sh_x[(r0+r)*164 + 16 + k];   // vn_p
                acc[r][0] = fmaf(xq, wq.x, acc[r][0]);
                acc[r][1] = fmaf(xq, wq.y, acc[r][1]);
                acc[r][2] = fmaf(xq, wq.z, acc[r][2]);
                acc[r][3] = fmaf(xq, wq.w, acc[r][3]);
                accp[r]   = fmaf(xp, wp,   accp[r]);
            }
        }
        float4 bq  = __ldg(&((const float4*)q_ws_b)[L]);
        float4 wsq = __ldg(&((const float4*)attn_ws_w)[L & 7]);  // ws_q[4*(L&7) ..]
        float  bp  = __ldg(&wp_ws_b[L]);
        #pragma unroll
        for (int r = 0; r < 4; r++){
            const int p = pr0 + r0 + r;
            float so0 = acc[r][0]+bq.x, so1 = acc[r][1]+bq.y;
            float so2 = acc[r][2]+bq.z, so3 = acc[r][3]+bq.w;
            float sg0 = sigm(so0), sg1 = sigm(so1), sg2 = sigm(so2), sg3 = sigm(so3);
            *(float4*)&sh_x[(r0+r)*164 + 4*L] = make_float4(sg0, sg1, sg2, sg3);
            float pe = so0*sg0*wsq.x + so1*sg1*wsq.y + so2*sg2*wsq.z + so3*sg3*wsq.w;
            pe += __shfl_down_sync(0xffffffffu, pe, 4, 8);
            pe += __shfl_down_sync(0xffffffffu, pe, 2, 8);
            pe += __shfl_down_sync(0xffffffffu, pe, 1, 8);
            if ((L & 7) == 0) g_eq[(size_t)p*4 + (L >> 3)] = pe;
            g_e[(size_t)p*32 + L] = __expf(accp[r] + bp);
        }
    }
    __syncthreads();

    // ---- phase C1: gate, vo -> qv (into sh_v)
    {
        const int row = tid >> 3, g = tid & 7;
        float qvv[2][3];
        #pragma unroll
        for (int ii = 0; ii < 2; ii++){
            int i = g*2 + ii;
            float acc = sh_wsvb[i];
            for (int j = 0; j < 128; j++)
                acc = fmaf(sh_x[row*164 + j], sh_wsv[j*16 + i], acc);
            float gate = sigm(acc);
            #pragma unroll
            for (int d = 0; d < 3; d++){
                float vo = 0.f;
                #pragma unroll
                for (int k = 0; k < 16; k++)
                    vo = fmaf(sh_vh[row*49 + d*16 + k], sh_wv[k*16 + i], vo);
                qvv[ii][d] = vo * gate;
            }
        }
        #pragma unroll
        for (int ii = 0; ii < 2; ii++)
            #pragma unroll
            for (int d = 0; d < 3; d++)
                sh_v[row*49 + (g*2+ii)*3 + d] = qvv[ii][d];
    }
    __syncthreads();

    // ---- phase C2: qh[h][d][j], thread handles j = g
    {
        const int row = tid >> 3, g = tid & 7;
        const int p = pr0 + row;
        #pragma unroll
        for (int h = 0; h < 4; h++)
            #pragma unroll
            for (int d = 0; d < 3; d++){
                float acc = 0.f;
                #pragma unroll
                for (int m = 0; m < 4; m++)
                    acc = fmaf(sh_v[row*49 + (h*4+m)*3 + d], sh_whq[m*8 + g], acc);
                g_qh[(size_t)p*96 + h*24 + d*8 + g] = acc;
            }
    }
}

// ---------------- K2: pooled softmax reduction ----------------
// grid 132 (even). c = blockIdx.x&1 fixed per block. warp w owns d-slice [22w,22w+22), lane = r.
__global__ __launch_bounds__(256) void k_pool(
    const float* __restrict__ s, const float* __restrict__ v)
{
    __shared__ float sh_e[8][32];
    __shared__ float sh_x[8][176];
    const int tid = threadIdx.x, lane = tid & 31, w = tid >> 5;
    const int c  = blockIdx.x & 1;
    const int bi = blockIdx.x >> 1;

    float acc[22];
    #pragma unroll
    for (int j = 0; j < 22; j++) acc[j] = 0.f;
    float z = 0.f;

    for (int n0 = bi*8; n0 < N_; n0 += 66*8){
        for (int q = tid; q < 8*208; q += 256){
            int rr = q / 208, off = q - rr*208;
            int n = n0 + rr;
            if (off < 32){
                sh_e[rr][off] = (n < N_) ? g_e[((size_t)(n*2+c))*32 + off] : 0.f;
            } else if (n < N_){
                if (off < 160) sh_x[rr][off-32]  = s[((size_t)(n*2+c))*128 + off - 32];
                else           sh_x[rr][off-32]  = v[((size_t)(n*2+c))*48  + off - 160];
            }
        }
        __syncthreads();
        #pragma unroll
        for (int rr = 0; rr < 8; rr++){
            float e = sh_e[rr][lane];
            #pragma unroll
            for (int j = 0; j < 22; j++)
                acc[j] = fmaf(e, sh_x[rr][w*22 + j], acc[j]);
            if (w == 0) z += e;
        }
        __syncthreads();
    }
    float* dst = g_num + (size_t)(c*32 + lane)*176 + w*22;
    #pragma unroll
    for (int j = 0; j < 22; j++) atomicAdd(dst + j, acc[j]);
    if (w == 0) atomicAdd(&g_Z[c*32 + lane], z);
}

// ---------------- K3: k & vv GVPs on 64 pooled rows ----------------
__global__ __launch_bounds__(128) void k_small(
    const float* __restrict__ k_wh, const float* __restrict__ k_ws_w, const float* __restrict__ k_ws_b,
    const float* __restrict__ k_wv, const float* __restrict__ k_wsv_w, const float* __restrict__ k_wsv_b,
    const float* __restrict__ v_wh, const float* __restrict__ v_ws_w, const float* __restrict__ v_ws_b,
    const float* __restrict__ v_wv, const float* __restrict__ v_wsv_w, const float* __restrict__ v_wsv_b,
    const float* __restrict__ attn_wh, const float* __restrict__ attn_ws_w)
{
    __shared__ float sh_s[128], sh_vg[48];
    __shared__ float sh_vhk[48], sh_vhv[48], sh_vnk[16], sh_vnv[16];
    __shared__ float sh_gk[128], sh_gv[128], sh_kv[48];
    const int r = blockIdx.x, c = blockIdx.y, rc = r*2 + c;
    const int t = threadIdx.x;

    float invZ = 1.f / g_Z[c*32 + r];
    sh_s[t] = g_num[(c*32 + r)*176 + t] * invZ;
    if (t < 48) sh_vg[t] = g_num[(c*32 + r)*176 + 128 + t] * invZ;
    __syncthreads();

    if (t < 16){
        float a0=0,a1=0,a2=0, b0=0,b1=0,b2=0;
        #pragma unroll
        for (int kk = 0; kk < 16; kk++){
            float v0 = sh_vg[kk*3], v1 = sh_vg[kk*3+1], v2 = sh_vg[kk*3+2];
            float wa = __ldg(k_wh + kk*16 + t), wb = __ldg(v_wh + kk*16 + t);
            a0 = fmaf(v0,wa,a0); a1 = fmaf(v1,wa,a1); a2 = fmaf(v2,wa,a2);
            b0 = fmaf(v0,wb,b0); b1 = fmaf(v1,wb,b1); b2 = fmaf(v2,wb,b2);
        }
        sh_vhk[t] = a0; sh_vhk[16+t] = a1; sh_vhk[32+t] = a2;
        sh_vhv[t] = b0; sh_vhv[16+t] = b1; sh_vhv[32+t] = b2;
        sh_vnk[t] = sqrtf(fmaxf(a0*a0+a1*a1+a2*a2, EPSc));
        sh_vnv[t] = sqrtf(fmaxf(b0*b0+b1*b1+b2*b2, EPSc));
    }
    __syncthreads();

    float sa = __ldg(k_ws_b + t), sb = __ldg(v_ws_b + t);
    for (int m = 0; m < 128; m++){
        float x = sh_s[m];
        sa = fmaf(x, __ldg(k_ws_w + m*128 + t), sa);
        sb = fmaf(x, __ldg(v_ws_w + m*128 + t), sb);
    }
    #pragma unroll
    for (int m = 0; m < 16; m++){
        sa = fmaf(sh_vnk[m], __ldg(k_ws_w + (128+m)*128 + t), sa);
        sb = fmaf(sh_vnv[m], __ldg(v_ws_w + (128+m)*128 + t), sb);
    }
    float ga = sigm(sa), gb = sigm(sb);
    sh_gk[t] = ga; sh_gv[t] = gb;
    g_vs[rc*128 + t] = sb * gb;                 // vs = silu(so_v)
    // ek = silu(so_k) . ws_k  per head (head = warp id)
    float part = (sa*ga) * __ldg(attn_ws_w + 32 + (t & 31));
    #pragma unroll
    for (int off = 16; off; off >>= 1) part += __shfl_down_sync(0xffffffffu, part, off);
    if ((t & 31) == 0) g_ek[rc*4 + (t >> 5)] = part;
    __syncthreads();

    if (t < 16){
        float ak = __ldg(k_wsv_b + t), av = __ldg(v_wsv_b + t);
        for (int j = 0; j < 128; j++){
            ak = fmaf(sh_gk[j], __ldg(k_wsv_w + j*16 + t), ak);
            av = fmaf(sh_gv[j], __ldg(v_wsv_w + j*16 + t), av);
        }
        float gk = sigm(ak), gv = sigm(av);
        #pragma unroll
        for (int d = 0; d < 3; d++){
            float voa = 0.f, vob = 0.f;
            #pragma unroll
            for (int kk = 0; kk < 16; kk++){
                voa = fmaf(sh_vhk[d*16 + kk], __ldg(k_wv + kk*16 + t), voa);
                vob = fmaf(sh_vhv[d*16 + kk], __ldg(v_wv + kk*16 + t), vob);
            }
            sh_kv[t*3 + d] = voa * gk;
            g_vv[rc*48 + t*3 + d] = vob * gv;   // layout == h*12 + dv*3 + d
        }
    }
    __syncthreads();

    if (t < 8){
        #pragma unroll
        for (int h = 0; h < 4; h++)
            #pragma unroll
            for (int d = 0; d < 3; d++){
                float acc = 0.f;
                #pragma unroll
                for (int m = 0; m < 4; m++)
                    acc = fmaf(sh_kv[(h*4+m)*3 + d], __ldg(attn_wh + (4+m)*8 + t), acc);
                g_kh[rc*96 + h*24 + d*8 + t] = acc;
            }
    }
}

// ---------------- K4: attention ----------------
// grid (296, 2): blockIdx.y = c. warp per (n, h) task; lane = r.
__global__ __launch_bounds__(256) void k_attn(
    const float* __restrict__ attn_ws_w, const float* __restrict__ attn_ws_b,
    float* __restrict__ out_s, float* __restrict__ out_v)
{
    __shared__ float kh_s[32*96];
    __shared__ float vs_s[32*128];
    __shared__ float vv_s[32*48];
    __shared__ float ek_s[128];
    const int c = blockIdx.y, tid = threadIdx.x, lane = tid & 31, w = tid >> 5;

    for (int idx = tid; idx < 3072; idx += 256){ int r = idx/96;  kh_s[idx] = g_kh[(r*2+c)*96  + idx - r*96 ]; }
    for (int idx = tid; idx < 4096; idx += 256){ int r = idx>>7;  vs_s[idx] = g_vs[(r*2+c)*128 + (idx & 127)]; }
    for (int idx = tid; idx < 1536; idx += 256){ int r = idx/48;  vv_s[idx] = g_vv[(r*2+c)*48  + idx - r*48 ]; }
    if (tid < 128) ek_s[tid] = g_ek[((tid>>2)*2 + c)*4 + (tid & 3)];
    __syncthreads();

    float wn[8];
    #pragma unroll
    for (int j = 0; j < 8; j++) wn[j] = __ldg(attn_ws_w + 64 + j);
    const float bias = __ldg(attn_ws_b);
    const float sc = 0.17677669529663687f;   // 1/sqrt(32)
    const int   jv = (lane < 12) ? lane : 0;

    for (int task = blockIdx.x*8 + w; task < 40000; task += gridDim.x*8){
        const int n = task >> 2, h = task & 3;
        const int p = n*2 + c;

        float q[24];
        const float* qp = g_qh + (size_t)p*96 + h*24;
        #pragma unroll
        for (int j = 0; j < 24; j++) q[j] = __ldg(qp + j);

        float kh[24];
        const float4* k4 = (const float4*)(kh_s + lane*96 + h*24);
        #pragma unroll
        for (int j = 0; j < 6; j++){
            float4 t4 = k4[j];
            kh[j*4] = t4.x; kh[j*4+1] = t4.y; kh[j*4+2] = t4.z; kh[j*4+3] = t4.w;
        }

        float e = __ldg(&g_eq[(size_t)p*4 + h]) + ek_s[lane*4 + h] + bias;
        #pragma unroll
        for (int j = 0; j < 8; j++){
            float s0 = q[j]    + kh[j];
            float s1 = q[8+j]  + kh[8+j];
            float s2 = q[16+j] + kh[16+j];
            float ss = fmaf(s0,s0, fmaf(s1,s1, s2*s2));
            e = fmaf(sqrtf(fmaxf(ss, EPSc)), wn[j], e);
        }
        e *= sc;

        float m = e;
        #pragma unroll
        for (int off = 16; off; off >>= 1) m = fmaxf(m, __shfl_xor_sync(0xffffffffu, m, off));
        float ex = __expf(e - m);
        float z = ex;
        #pragma unroll
        for (int off = 16; off; off >>= 1) z += __shfl_xor_sync(0xffffffffu, z, off);
        float alpha = ex / z;

        float accs = 0.f, accv = 0.f;
        const float* vsb = vs_s + h*32 + lane;
        const float* vvb = vv_s + h*12 + jv;
        #pragma unroll
        for (int r2 = 0; r2 < 32; r2++){
            float a = __shfl_sync(0xffffffffu, alpha, r2);
            accs = fmaf(a, vsb[r2*128], accs);
            accv = fmaf(a, vvb[r2*48],  accv);
        }
        out_s[(size_t)p*128 + h*32 + lane] = accs;
        if (lane < 12) out_v[(size_t)p*48 + h*12 + lane] = accv;
    }
}

// ---------------- launch ----------------
extern "C" void kernel_launch(void* const* d_in, const int* in_sizes, int n_in,
                              void* d_out, int out_size)
{
    const float* s        = (const float*)d_in[0];
    const float* v        = (const float*)d_in[1];
    const float* wp_wh    = (const float*)d_in[2];
    const float* wp_ws_w  = (const float*)d_in[3];
    const float* wp_ws_b  = (const float*)d_in[4];
    const float* q_wh     = (const float*)d_in[5];
    const float* q_ws_w   = (const float*)d_in[6];
    const float* q_ws_b   = (const float*)d_in[7];
    const float* q_wv     = (const float*)d_in[8];
    const float* q_wsv_w  = (const float*)d_in[9];
    const float* q_wsv_b  = (const float*)d_in[10];
    const float* k_wh     = (const float*)d_in[11];
    const float* k_ws_w   = (const float*)d_in[12];
    const float* k_ws_b   = (const float*)d_in[13];
    const float* k_wv     = (const float*)d_in[14];
    const float* k_wsv_w  = (const float*)d_in[15];
    const float* k_wsv_b  = (const float*)d_in[16];
    const float* vv_wh    = (const float*)d_in[17];
    const float* vv_ws_w  = (const float*)d_in[18];
    const float* vv_ws_b  = (const float*)d_in[19];
    const float* vv_wv    = (const float*)d_in[20];
    const float* vv_wsv_w = (const float*)d_in[21];
    const float* vv_wsv_b = (const float*)d_in[22];
    const float* attn_wh  = (const float*)d_in[23];
    const float* attn_ws_w= (const float*)d_in[24];
    const float* attn_ws_b= (const float*)d_in[25];

    float* out_s = (float*)d_out;
    float* out_v = out_s + (size_t)P_*128;   // out_s (N,C,128) then out_v (N,C,16,3)

    k_init <<<12, 256>>>();
    k_main <<<625, 256>>>(s, v, wp_wh, wp_ws_w, wp_ws_b,
                          q_wh, q_ws_w, q_ws_b, q_wv, q_wsv_w, q_wsv_b,
                          attn_wh, attn_ws_w);
    k_pool <<<132, 256>>>(s, v);
    k_small<<<dim3(32,2), 128>>>(k_wh, k_ws_w, k_ws_b, k_wv, k_wsv_w, k_wsv_b,
                                 vv_wh, vv_ws_w, vv_ws_b, vv_wv, vv_wsv_w, vv_wsv_b,
                                 attn_wh, attn_ws_w);
    k_attn <<<dim3(296,2), 256>>>(attn_ws_w, attn_ws_b, out_s, out_v);
}

// round 16
// speedup vs baseline: 1.1879x; 1.1879x over previous
#include <cuda_runtime.h>
#include <math.h>

#define N_  10000
#define P_  20000
#define EPSc 1e-8f

// ---------------- scratch (device globals, no allocation) ----------------
__device__ __align__(16) float g_e  [P_*32];           // exp(pool logits)
__device__ __align__(16) float g_eq [P_*4];            // qs . ws_q per head
__device__ __align__(16) float g_qh [(size_t)P_*96];   // qh [p][h][d][j]
__device__ __align__(16) float g_num[2*32*176];        // pooled numerators [c][r][s(128)|v(48)]
__device__ __align__(16) float g_Z  [64];              // pooled softmax denominators [c][r]
__device__ __align__(16) float g_ek [64*4];            // ks . ws_k   [rc][h]
__device__ __align__(16) float g_kh [64*96];           // kh [rc][h][d][j]
__device__ __align__(16) float g_vs [64*128];          // silu(so_v)  [rc][128]
__device__ __align__(16) float g_vv [64*48];           // gated vv    [rc][i*3+d]

__device__ __forceinline__ float sigm(float x){ return 1.f/(1.f+__expf(-x)); }

// ---- packed f32x2 helpers ----
__device__ __forceinline__ unsigned long long pk(float a, float b){
    unsigned long long r; asm("mov.b64 %0,{%1,%2};" : "=l"(r) : "f"(a), "f"(b)); return r;
}
__device__ __forceinline__ void fma2(unsigned long long& d, unsigned long long a, unsigned long long b){
    asm("fma.rn.f32x2 %0,%1,%2,%0;" : "+l"(d) : "l"(a), "l"(b));
}
__device__ __forceinline__ float2 unpk(unsigned long long x){
    float2 r; asm("mov.b64 {%0,%1},%2;" : "=f"(r.x), "=f"(r.y) : "l"(x)); return r;
}

// ---------------- K0: zero accumulators ----------------
__global__ void k_init(){
    int i = blockIdx.x*blockDim.x + threadIdx.x;
    const int tot = 2*32*176 + 64;
    for (; i < tot; i += gridDim.x*blockDim.x){
        if (i < 2*32*176) g_num[i] = 0.f;
        else              g_Z[i - 2*32*176] = 0.f;
    }
}

// ---------------- K1: per-row q-GVP + pooling logits ----------------
// 32 rows/block, 256 threads.
__global__ __launch_bounds__(256) void k_main(
    const float* __restrict__ s, const float* __restrict__ v,
    const float* __restrict__ wp_wh, const float* __restrict__ wp_ws_w, const float* __restrict__ wp_ws_b,
    const float* __restrict__ q_wh,  const float* __restrict__ q_ws_w,  const float* __restrict__ q_ws_b,
    const float* __restrict__ q_wv,  const float* __restrict__ q_wsv_w, const float* __restrict__ q_wsv_b,
    const float* __restrict__ attn_wh, const float* __restrict__ attn_ws_w)
{
    __shared__ __align__(16) float sh_x [32*164];  // s(0..127)->later sigmoid(so); vn_q(128..143); vn_p(144..159)
    __shared__ __align__(16) float sh_v [32*49];   // raw v, later qv[i*3+d]
    __shared__ __align__(16) float sh_vh[32*49];   // vh_q [d*16+i]
    __shared__ float sh_wsv[2048];
    __shared__ float sh_wv[256], sh_qwh[256], sh_pwh[256];
    __shared__ float sh_whq[64], sh_wsvb[16];

    const int tid = threadIdx.x;
    const int pr0 = blockIdx.x * 32;

    for (int i = tid; i < 2048; i += 256) sh_wsv[i] = q_wsv_w[i];
    sh_wv[tid]  = q_wv[tid];
    sh_qwh[tid] = q_wh[tid];
    sh_pwh[tid] = wp_wh[tid];
    if (tid < 64) sh_whq[tid]  = attn_wh[tid];
    if (tid < 16) sh_wsvb[tid] = q_wsv_b[tid];

    {   // stage s rows (float4)
        const float4* s4 = (const float4*)(s + (size_t)pr0*128);
        #pragma unroll
        for (int it = 0; it < 4; it++){
            int idx = tid + it*256;                // 0..1023 float4s
            float4 val = __ldg(&s4[idx]);
            int row = idx >> 5, c4 = idx & 31;
            *(float4*)&sh_x[row*164 + c4*4] = val;
        }
        // stage v rows
        const float* vsrc = v + (size_t)pr0*48;
        #pragma unroll
        for (int it = 0; it < 6; it++){
            int idx = tid + it*256;                // 0..1535
            sh_v[(idx/48)*49 + idx%48] = __ldg(vsrc + idx);
        }
    }
    __syncthreads();

    // ---- phase A: vh (q & pool) + norms. 8 threads/row, thread handles 2 i's.
    {
        const int row = tid >> 3, g = tid & 7;
        #pragma unroll
        for (int ii = 0; ii < 2; ii++){
            int i = g*2 + ii;
            float aq0=0,aq1=0,aq2=0, ap0=0,ap1=0,ap2=0;
            #pragma unroll
            for (int k = 0; k < 16; k++){
                float wq = sh_qwh[k*16+i], wp = sh_pwh[k*16+i];
                float v0 = sh_v[row*49 + k*3+0];
                float v1 = sh_v[row*49 + k*3+1];
                float v2 = sh_v[row*49 + k*3+2];
                aq0 = fmaf(v0,wq,aq0); aq1 = fmaf(v1,wq,aq1); aq2 = fmaf(v2,wq,aq2);
                ap0 = fmaf(v0,wp,ap0); ap1 = fmaf(v1,wp,ap1); ap2 = fmaf(v2,wp,ap2);
            }
            sh_vh[row*49 +  0 + i] = aq0;
            sh_vh[row*49 + 16 + i] = aq1;
            sh_vh[row*49 + 32 + i] = aq2;
            sh_x[row*164 + 128 + i] = sqrtf(fmaxf(aq0*aq0+aq1*aq1+aq2*aq2, EPSc));
            sh_x[row*164 + 144 + i] = sqrtf(fmaxf(ap0*ap0+ap1*ap1+ap2*ap2, EPSc));
        }
    }
    __syncthreads();

    // ---- phase B: so (144x128) + pool logits (144x32), f32x2-packed.
    // warp: 4 rows; lane: 4 so-cols + 1 pool-col.
    {
        const int w = tid >> 5, L = tid & 31, r0 = w*4;
        unsigned long long a01[4], a23[4], p01 = 0ull, p23 = 0ull;
        #pragma unroll
        for (int r = 0; r < 4; r++){ a01[r] = 0ull; a23[r] = 0ull; }
        const float4* Wq4 = (const float4*)q_ws_w;
        for (int k = 0; k < 128; k += 4){
            float4 xr[4];
            #pragma unroll
            for (int r = 0; r < 4; r++) xr[r] = *(const float4*)&sh_x[(r0+r)*164 + k];
            #pragma unroll
            for (int kk = 0; kk < 4; kk++){
                float4 wq = __ldg(&Wq4[(k+kk)*32 + L]);
                float  wp = __ldg(&wp_ws_w[(k+kk)*32 + L]);
                unsigned long long wq01 = pk(wq.x, wq.y);
                unsigned long long wq23 = pk(wq.z, wq.w);
                unsigned long long wpp  = pk(wp, wp);
                float xv[4];
                #pragma unroll
                for (int r = 0; r < 4; r++)
                    xv[r] = (kk==0)?xr[r].x:(kk==1)?xr[r].y:(kk==2)?xr[r].z:xr[r].w;
                #pragma unroll
                for (int r = 0; r < 4; r++){
                    unsigned long long xx = pk(xv[r], xv[r]);
                    fma2(a01[r], xx, wq01);
                    fma2(a23[r], xx, wq23);
                }
                fma2(p01, pk(xv[0], xv[1]), wpp);
                fma2(p23, pk(xv[2], xv[3]), wpp);
            }
        }
        #pragma unroll
        for (int k = 128; k < 144; k++){
            float4 wq = __ldg(&Wq4[k*32 + L]);
            float  wp = __ldg(&wp_ws_w[k*32 + L]);
            unsigned long long wq01 = pk(wq.x, wq.y);
            unsigned long long wq23 = pk(wq.z, wq.w);
            unsigned long long wpp  = pk(wp, wp);
            float xq[4], xp[4];
            #pragma unroll
            for (int r = 0; r < 4; r++){
                xq[r] = sh_x[(r0+r)*164 + k];        // vn_q
                xp[r] = sh_x[(r0+r)*164 + 16 + k];   // vn_p
            }
            #pragma unroll
            for (int r = 0; r < 4; r++){
                unsigned long long xx = pk(xq[r], xq[r]);
                fma2(a01[r], xx, wq01);
                fma2(a23[r], xx, wq23);
            }
            fma2(p01, pk(xp[0], xp[1]), wpp);
            fma2(p23, pk(xp[2], xp[3]), wpp);
        }
        float4 bq  = __ldg(&((const float4*)q_ws_b)[L]);
        float4 wsq = __ldg(&((const float4*)attn_ws_w)[L & 7]);  // ws_q[4*(L&7) ..]
        float  bp  = __ldg(&wp_ws_b[L]);
        float2 pp01 = unpk(p01), pp23 = unpk(p23);
        float accp[4] = { pp01.x, pp01.y, pp23.x, pp23.y };
        #pragma unroll
        for (int r = 0; r < 4; r++){
            const int p = pr0 + r0 + r;
            float2 s01 = unpk(a01[r]), s23 = unpk(a23[r]);
            float so0 = s01.x+bq.x, so1 = s01.y+bq.y;
            float so2 = s23.x+bq.z, so3 = s23.y+bq.w;
            float sg0 = sigm(so0), sg1 = sigm(so1), sg2 = sigm(so2), sg3 = sigm(so3);
            *(float4*)&sh_x[(r0+r)*164 + 4*L] = make_float4(sg0, sg1, sg2, sg3);
            float pe = so0*sg0*wsq.x + so1*sg1*wsq.y + so2*sg2*wsq.z + so3*sg3*wsq.w;
            pe += __shfl_down_sync(0xffffffffu, pe, 4, 8);
            pe += __shfl_down_sync(0xffffffffu, pe, 2, 8);
            pe += __shfl_down_sync(0xffffffffu, pe, 1, 8);
            if ((L & 7) == 0) g_eq[(size_t)p*4 + (L >> 3)] = pe;
            g_e[(size_t)p*32 + L] = __expf(accp[r] + bp);
        }
    }
    __syncthreads();

    // ---- phase C1: gate, vo -> qv (into sh_v)
    {
        const int row = tid >> 3, g = tid & 7;
        float qvv[2][3];
        #pragma unroll
        for (int ii = 0; ii < 2; ii++){
            int i = g*2 + ii;
            float acc = sh_wsvb[i];
            #pragma unroll 8
            for (int j = 0; j < 128; j++)
                acc = fmaf(sh_x[row*164 + j], sh_wsv[j*16 + i], acc);
            float gate = sigm(acc);
            #pragma unroll
            for (int d = 0; d < 3; d++){
                float vo = 0.f;
                #pragma unroll
                for (int k = 0; k < 16; k++)
                    vo = fmaf(sh_vh[row*49 + d*16 + k], sh_wv[k*16 + i], vo);
                qvv[ii][d] = vo * gate;
            }
        }
        #pragma unroll
        for (int ii = 0; ii < 2; ii++)
            #pragma unroll
            for (int d = 0; d < 3; d++)
                sh_v[row*49 + (g*2+ii)*3 + d] = qvv[ii][d];
    }
    __syncthreads();

    // ---- phase C2: qh[h][d][j], thread handles j = g
    {
        const int row = tid >> 3, g = tid & 7;
        const int p = pr0 + row;
        #pragma unroll
        for (int h = 0; h < 4; h++)
            #pragma unroll
            for (int d = 0; d < 3; d++){
                float acc = 0.f;
                #pragma unroll
                for (int m = 0; m < 4; m++)
                    acc = fmaf(sh_v[row*49 + (h*4+m)*3 + d], sh_whq[m*8 + g], acc);
                g_qh[(size_t)p*96 + h*24 + d*8 + g] = acc;
            }
    }
}

// ---------------- K2: pooled softmax reduction ----------------
__global__ __launch_bounds__(256) void k_pool(
    const float* __restrict__ s, const float* __restrict__ v)
{
    __shared__ float sh_e[8][32];
    __shared__ float sh_x[8][176];
    const int tid = threadIdx.x, lane = tid & 31, w = tid >> 5;
    const int c  = blockIdx.x & 1;
    const int bi = blockIdx.x >> 1;

    float acc[22];
    #pragma unroll
    for (int j = 0; j < 22; j++) acc[j] = 0.f;
    float z = 0.f;

    for (int n0 = bi*8; n0 < N_; n0 += 66*8){
        for (int q = tid; q < 8*208; q += 256){
            int rr = q / 208, off = q - rr*208;
            int n = n0 + rr;
            if (off < 32){
                sh_e[rr][off] = (n < N_) ? g_e[((size_t)(n*2+c))*32 + off] : 0.f;
            } else if (n < N_){
                if (off < 160) sh_x[rr][off-32]  = s[((size_t)(n*2+c))*128 + off - 32];
                else           sh_x[rr][off-32]  = v[((size_t)(n*2+c))*48  + off - 160];
            }
        }
        __syncthreads();
        #pragma unroll
        for (int rr = 0; rr < 8; rr++){
            float e = sh_e[rr][lane];
            #pragma unroll
            for (int j = 0; j < 22; j++)
                acc[j] = fmaf(e, sh_x[rr][w*22 + j], acc[j]);
            if (w == 0) z += e;
        }
        __syncthreads();
    }
    float* dst = g_num + (size_t)(c*32 + lane)*176 + w*22;
    #pragma unroll
    for (int j = 0; j < 22; j++) atomicAdd(dst + j, acc[j]);
    if (w == 0) atomicAdd(&g_Z[c*32 + lane], z);
}

// ---------------- K3: k & vv GVPs on 64 pooled rows ----------------
// 256 threads: t<128 does the k-GEMV col t, t>=128 the v-GEMV col t-128.
__global__ __launch_bounds__(256) void k_small(
    const float* __restrict__ k_wh, const float* __restrict__ k_ws_w, const float* __restrict__ k_ws_b,
    const float* __restrict__ k_wv, const float* __restrict__ k_wsv_w, const float* __restrict__ k_wsv_b,
    const float* __restrict__ v_wh, const float* __restrict__ v_ws_w, const float* __restrict__ v_ws_b,
    const float* __restrict__ v_wv, const float* __restrict__ v_wsv_w, const float* __restrict__ v_wsv_b,
    const float* __restrict__ attn_wh, const float* __restrict__ attn_ws_w)
{
    __shared__ float sh_s[128], sh_vg[48];
    __shared__ float sh_vhk[48], sh_vhv[48], sh_vnk[16], sh_vnv[16];
    __shared__ float sh_g[256];   // sigmoid(so): [0..127]=k, [128..255]=v
    __shared__ float sh_kv[48];
    const int r = blockIdx.x, c = blockIdx.y, rc = r*2 + c;
    const int t = threadIdx.x;

    float invZ = 1.f / g_Z[c*32 + r];
    if (t < 128)       sh_s[t]       = g_num[(c*32 + r)*176 + t] * invZ;
    else if (t < 176)  sh_vg[t-128]  = g_num[(c*32 + r)*176 + t] * invZ;
    __syncthreads();

    if (t < 32){
        const bool isv = t >= 16; const int tt = t & 15;
        const float* wh = isv ? v_wh : k_wh;
        float a0=0,a1=0,a2=0;
        #pragma unroll
        for (int kk = 0; kk < 16; kk++){
            float wv_ = __ldg(wh + kk*16 + tt);
            a0 = fmaf(sh_vg[kk*3+0], wv_, a0);
            a1 = fmaf(sh_vg[kk*3+1], wv_, a1);
            a2 = fmaf(sh_vg[kk*3+2], wv_, a2);
        }
        float* vh = isv ? sh_vhv : sh_vhk;
        float* vn = isv ? sh_vnv : sh_vnk;
        vh[tt] = a0; vh[16+tt] = a1; vh[32+tt] = a2;
        vn[tt] = sqrtf(fmaxf(a0*a0+a1*a1+a2*a2, EPSc));
    }
    __syncthreads();

    {
        const bool isv = t >= 128; const int col = t & 127;
        const float* W = isv ? v_ws_w : k_ws_w;
        float acc = isv ? __ldg(v_ws_b + col) : __ldg(k_ws_b + col);
        #pragma unroll 8
        for (int m = 0; m < 128; m++)
            acc = fmaf(sh_s[m], __ldg(W + m*128 + col), acc);
        const float* vn = isv ? sh_vnv : sh_vnk;
        #pragma unroll
        for (int m = 0; m < 16; m++)
            acc = fmaf(vn[m], __ldg(W + (128+m)*128 + col), acc);
        float g = sigm(acc);
        sh_g[t] = g;
        if (isv){
            g_vs[rc*128 + col] = acc * g;            // silu(so_v)
        } else {
            // ek per head = sum over cols of silu(so_k)*ws_k ; head = col>>5 = warp id
            float part = (acc*g) * __ldg(attn_ws_w + 32 + (col & 31));
            #pragma unroll
            for (int off = 16; off; off >>= 1) part += __shfl_down_sync(0xffffffffu, part, off);
            if ((t & 31) == 0) g_ek[rc*4 + (t >> 5)] = part;
        }
    }
    __syncthreads();

    if (t < 32){
        const bool isv = t >= 16; const int tt = t & 15;
        const float* wsvw = isv ? v_wsv_w : k_wsv_w;
        float a = __ldg((isv ? v_wsv_b : k_wsv_b) + tt);
        const float* gg = sh_g + (isv ? 128 : 0);
        #pragma unroll 8
        for (int j = 0; j < 128; j++)
            a = fmaf(gg[j], __ldg(wsvw + j*16 + tt), a);
        float gate = sigm(a);
        const float* vh = isv ? sh_vhv : sh_vhk;
        const float* wv = isv ? v_wv : k_wv;
        #pragma unroll
        for (int d = 0; d < 3; d++){
            float vo = 0.f;
            #pragma unroll
            for (int kk = 0; kk < 16; kk++)
                vo = fmaf(vh[d*16 + kk], __ldg(wv + kk*16 + tt), vo);
            if (isv) g_vv[rc*48 + tt*3 + d] = vo * gate;   // layout == h*12 + dv*3 + d
            else     sh_kv[tt*3 + d] = vo * gate;
        }
    }
    __syncthreads();

    if (t < 8){
        #pragma unroll
        for (int h = 0; h < 4; h++)
            #pragma unroll
            for (int d = 0; d < 3; d++){
                float acc = 0.f;
                #pragma unroll
                for (int m = 0; m < 4; m++)
                    acc = fmaf(sh_kv[(h*4+m)*3 + d], __ldg(attn_wh + (4+m)*8 + t), acc);
                g_kh[rc*96 + h*24 + d*8 + t] = acc;
            }
    }
}

// ---------------- K4: attention ----------------
// grid (250, 2): blockIdx.y = c. Warp: fixed h = w&3; processes groups of 4 n.
// lane = r. kh hoisted per warp; vs/vv LDS amortized over 4 tasks.
__global__ __launch_bounds__(256) void k_attn(
    const float* __restrict__ attn_ws_w, const float* __restrict__ attn_ws_b,
    float* __restrict__ out_s, float* __restrict__ out_v)
{
    __shared__ float kh_s[32*96];
    __shared__ float vs_s[32*128];
    __shared__ float vv_s[32*48];
    __shared__ float ek_s[128];
    const int c = blockIdx.y, tid = threadIdx.x, lane = tid & 31, w = tid >> 5;

    for (int idx = tid; idx < 3072; idx += 256){ int r = idx/96;  kh_s[idx] = g_kh[(r*2+c)*96  + idx - r*96 ]; }
    for (int idx = tid; idx < 4096; idx += 256){ int r = idx>>7;  vs_s[idx] = g_vs[(r*2+c)*128 + (idx & 127)]; }
    for (int idx = tid; idx < 1536; idx += 256){ int r = idx/48;  vv_s[idx] = g_vv[(r*2+c)*48  + idx - r*48 ]; }
    if (tid < 128) ek_s[tid] = g_ek[((tid>>2)*2 + c)*4 + (tid & 3)];
    __syncthreads();

    const int h = w & 3, g2 = w >> 2;

    // per-warp constants: kh for (lane=r, h)
    float kh[24];
    {
        const float4* k4 = (const float4*)(kh_s + lane*96 + h*24);
        #pragma unroll
        for (int j = 0; j < 6; j++){
            float4 t4 = k4[j];
            kh[j*4] = t4.x; kh[j*4+1] = t4.y; kh[j*4+2] = t4.z; kh[j*4+3] = t4.w;
        }
    }
    float wn[8];
    #pragma unroll
    for (int j = 0; j < 8; j++) wn[j] = __ldg(attn_ws_w + 64 + j);
    const float ekb = ek_s[lane*4 + h] + __ldg(attn_ws_b);
    const float sc = 0.17677669529663687f;   // 1/sqrt(32)
    const int   jv = (lane < 12) ? lane : 0;
    const float* vsb = vs_s + h*32 + lane;
    const float* vvb = vv_s + h*12 + jv;

    for (int grp = blockIdx.x*2 + g2; grp < 2500; grp += gridDim.x*2){
        const int nbase = grp * 4;
        float alpha[4];
        #pragma unroll
        for (int t4 = 0; t4 < 4; t4++){
            const int p = (nbase + t4)*2 + c;
            float q[24];
            const float4* qp = (const float4*)(g_qh + (size_t)p*96 + h*24);
            #pragma unroll
            for (int j = 0; j < 6; j++){
                float4 v4 = __ldg(&qp[j]);
                q[j*4] = v4.x; q[j*4+1] = v4.y; q[j*4+2] = v4.z; q[j*4+3] = v4.w;
            }
            float e = __ldg(&g_eq[(size_t)p*4 + h]) + ekb;
            #pragma unroll
            for (int j = 0; j < 8; j++){
                float s0 = q[j]    + kh[j];
                float s1 = q[8+j]  + kh[8+j];
                float s2 = q[16+j] + kh[16+j];
                float ss = fmaf(s0,s0, fmaf(s1,s1, s2*s2));
                e = fmaf(sqrtf(fmaxf(ss, EPSc)), wn[j], e);
            }
            e *= sc;
            float m = e;
            #pragma unroll
            for (int off = 16; off; off >>= 1) m = fmaxf(m, __shfl_xor_sync(0xffffffffu, m, off));
            float ex = __expf(e - m);
            float z = ex;
            #pragma unroll
            for (int off = 16; off; off >>= 1) z += __shfl_xor_sync(0xffffffffu, z, off);
            alpha[t4] = ex / z;
        }

        float accs[4] = {0,0,0,0}, accv[4] = {0,0,0,0};
        #pragma unroll
        for (int r2 = 0; r2 < 32; r2++){
            float vsv = vsb[r2*128];
            float vvv = vvb[r2*48];
            #pragma unroll
            for (int t4 = 0; t4 < 4; t4++){
                float a = __shfl_sync(0xffffffffu, alpha[t4], r2);
                accs[t4] = fmaf(a, vsv, accs[t4]);
                accv[t4] = fmaf(a, vvv, accv[t4]);
            }
        }
        #pragma unroll
        for (int t4 = 0; t4 < 4; t4++){
            const int p = (nbase + t4)*2 + c;
            out_s[(size_t)p*128 + h*32 + lane] = accs[t4];
            if (lane < 12) out_v[(size_t)p*48 + h*12 + lane] = accv[t4];
        }
    }
}

// ---------------- launch ----------------
extern "C" void kernel_launch(void* const* d_in, const int* in_sizes, int n_in,
                              void* d_out, int out_size)
{
    const float* s        = (const float*)d_in[0];
    const float* v        = (const float*)d_in[1];
    const float* wp_wh    = (const float*)d_in[2];
    const float* wp_ws_w  = (const float*)d_in[3];
    const float* wp_ws_b  = (const float*)d_in[4];
    const float* q_wh     = (const float*)d_in[5];
    const float* q_ws_w   = (const float*)d_in[6];
    const float* q_ws_b   = (const float*)d_in[7];
    const float* q_wv     = (const float*)d_in[8];
    const float* q_wsv_w  = (const float*)d_in[9];
    const float* q_wsv_b  = (const float*)d_in[10];
    const float* k_wh     = (const float*)d_in[11];
    const float* k_ws_w   = (const float*)d_in[12];
    const float* k_ws_b   = (const float*)d_in[13];
    const float* k_wv     = (const float*)d_in[14];
    const float* k_wsv_w  = (const float*)d_in[15];
    const float* k_wsv_b  = (const float*)d_in[16];
    const float* vv_wh    = (const float*)d_in[17];
    const float* vv_ws_w  = (const float*)d_in[18];
    const float* vv_ws_b  = (const float*)d_in[19];
    const float* vv_wv    = (const float*)d_in[20];
    const float* vv_wsv_w = (const float*)d_in[21];
    const float* vv_wsv_b = (const float*)d_in[22];
    const float* attn_wh  = (const float*)d_in[23];
    const float* attn_ws_w= (const float*)d_in[24];
    const float* attn_ws_b= (const float*)d_in[25];

    float* out_s = (float*)d_out;
    float* out_v = out_s + (size_t)P_*128;   // out_s (N,C,128) then out_v (N,C,16,3)

    k_init <<<12, 256>>>();
    k_main <<<625, 256>>>(s, v, wp_wh, wp_ws_w, wp_ws_b,
                          q_wh, q_ws_w, q_ws_b, q_wv, q_wsv_w, q_wsv_b,
                          attn_wh, attn_ws_w);
    k_pool <<<132, 256>>>(s, v);
    k_small<<<dim3(32,2), 256>>>(k_wh, k_ws_w, k_ws_b, k_wv, k_wsv_w, k_wsv_b,
                                 vv_wh, vv_ws_w, vv_ws_b, vv_wv, vv_wsv_w, vv_wsv_b,
                                 attn_wh, attn_ws_w);
    k_attn <<<dim3(250,2), 256>>>(attn_ws_w, attn_ws_b, out_s, out_v);
}

// round 17
// speedup vs baseline: 1.2571x; 1.0583x over previous
#include <cuda_runtime.h>
#include <math.h>

#define N_  10000
#define P_  20000
#define EPSc 1e-8f

// ---------------- scratch (device globals, no allocation) ----------------
__device__ __align__(16) float g_e  [P_*32];           // exp(pool logits)
__device__ __align__(16) float g_eq [P_*4];            // qs . ws_q per head
__device__ __align__(16) float g_qh [(size_t)P_*96];   // qh [p][h][d][j]
__device__ __align__(16) float g_num[2*32*176];        // pooled numerators [c][r][s(128)|v(48)]
__device__ __align__(16) float g_Z  [64];              // pooled softmax denominators [c][r]
__device__ __align__(16) float g_ek [64*4];            // ks . ws_k   [rc][h]
__device__ __align__(16) float g_kh [64*96];           // kh [rc][h][d][j]
__device__ __align__(16) float g_vs [64*128];          // silu(so_v)  [rc][128]
__device__ __align__(16) float g_vv [64*48];           // gated vv    [rc][i*3+d]

__device__ __forceinline__ float sigm(float x){ return 1.f/(1.f+__expf(-x)); }

// ---- packed f32x2 helpers ----
__device__ __forceinline__ unsigned long long pk(float a, float b){
    unsigned long long r; asm("mov.b64 %0,{%1,%2};" : "=l"(r) : "f"(a), "f"(b)); return r;
}
__device__ __forceinline__ void fma2(unsigned long long& d, unsigned long long a, unsigned long long b){
    asm("fma.rn.f32x2 %0,%1,%2,%0;" : "+l"(d) : "l"(a), "l"(b));
}
__device__ __forceinline__ float2 unpk(unsigned long long x){
    float2 r; asm("mov.b64 {%0,%1},%2;" : "=f"(r.x), "=f"(r.y) : "l"(x)); return r;
}

// ---------------- K0: zero accumulators ----------------
__global__ void k_init(){
    int i = blockIdx.x*blockDim.x + threadIdx.x;
    const int tot = 2*32*176 + 64;
    for (; i < tot; i += gridDim.x*blockDim.x){
        if (i < 2*32*176) g_num[i] = 0.f;
        else              g_Z[i - 2*32*176] = 0.f;
    }
}

// ---------------- K1: per-row q-GVP + pooling logits ----------------
// 32 rows/block, 256 threads.
__global__ __launch_bounds__(256) void k_main(
    const float* __restrict__ s, const float* __restrict__ v,
    const float* __restrict__ wp_wh, const float* __restrict__ wp_ws_w, const float* __restrict__ wp_ws_b,
    const float* __restrict__ q_wh,  const float* __restrict__ q_ws_w,  const float* __restrict__ q_ws_b,
    const float* __restrict__ q_wv,  const float* __restrict__ q_wsv_w, const float* __restrict__ q_wsv_b,
    const float* __restrict__ attn_wh, const float* __restrict__ attn_ws_w)
{
    __shared__ __align__(16) float sh_x [32*164];  // s(0..127)->later sigmoid(so); vn_q(128..143); vn_p(144..159)
    __shared__ __align__(16) float sh_v [32*49];   // raw v, later qv[i*3+d]
    __shared__ __align__(16) float sh_vh[32*49];   // vh_q [d*16+i]
    __shared__ float sh_wsv[2048];
    __shared__ float sh_wv[256], sh_qwh[256], sh_pwh[256];
    __shared__ float sh_whq[64], sh_wsvb[16];

    const int tid = threadIdx.x;
    const int pr0 = blockIdx.x * 32;

    for (int i = tid; i < 2048; i += 256) sh_wsv[i] = q_wsv_w[i];
    sh_wv[tid]  = q_wv[tid];
    sh_qwh[tid] = q_wh[tid];
    sh_pwh[tid] = wp_wh[tid];
    if (tid < 64) sh_whq[tid]  = attn_wh[tid];
    if (tid < 16) sh_wsvb[tid] = q_wsv_b[tid];

    {   // stage s rows (float4)
        const float4* s4 = (const float4*)(s + (size_t)pr0*128);
        #pragma unroll
        for (int it = 0; it < 4; it++){
            int idx = tid + it*256;                // 0..1023 float4s
            float4 val = __ldg(&s4[idx]);
            int row = idx >> 5, c4 = idx & 31;
            *(float4*)&sh_x[row*164 + c4*4] = val;
        }
        // stage v rows
        const float* vsrc = v + (size_t)pr0*48;
        #pragma unroll
        for (int it = 0; it < 6; it++){
            int idx = tid + it*256;                // 0..1535
            sh_v[(idx/48)*49 + idx%48] = __ldg(vsrc + idx);
        }
    }
    __syncthreads();

    // ---- phase A: vh (q & pool) + norms. 8 threads/row, thread handles 2 i's.
    {
        const int row = tid >> 3, g = tid & 7;
        #pragma unroll
        for (int ii = 0; ii < 2; ii++){
            int i = g*2 + ii;
            float aq0=0,aq1=0,aq2=0, ap0=0,ap1=0,ap2=0;
            #pragma unroll
            for (int k = 0; k < 16; k++){
                float wq = sh_qwh[k*16+i], wp = sh_pwh[k*16+i];
                float v0 = sh_v[row*49 + k*3+0];
                float v1 = sh_v[row*49 + k*3+1];
                float v2 = sh_v[row*49 + k*3+2];
                aq0 = fmaf(v0,wq,aq0); aq1 = fmaf(v1,wq,aq1); aq2 = fmaf(v2,wq,aq2);
                ap0 = fmaf(v0,wp,ap0); ap1 = fmaf(v1,wp,ap1); ap2 = fmaf(v2,wp,ap2);
            }
            sh_vh[row*49 +  0 + i] = aq0;
            sh_vh[row*49 + 16 + i] = aq1;
            sh_vh[row*49 + 32 + i] = aq2;
            sh_x[row*164 + 128 + i] = sqrtf(fmaxf(aq0*aq0+aq1*aq1+aq2*aq2, EPSc));
            sh_x[row*164 + 144 + i] = sqrtf(fmaxf(ap0*ap0+ap1*ap1+ap2*ap2, EPSc));
        }
    }
    __syncthreads();

    // ---- phase B: so (144x128) + pool logits (144x32), f32x2-packed.
    // warp: 4 rows; lane: 4 so-cols + 1 pool-col.
    {
        const int w = tid >> 5, L = tid & 31, r0 = w*4;
        unsigned long long a01[4], a23[4], p01 = 0ull, p23 = 0ull;
        #pragma unroll
        for (int r = 0; r < 4; r++){ a01[r] = 0ull; a23[r] = 0ull; }
        const float4* Wq4 = (const float4*)q_ws_w;
        for (int k = 0; k < 128; k += 4){
            float4 xr[4];
            #pragma unroll
            for (int r = 0; r < 4; r++) xr[r] = *(const float4*)&sh_x[(r0+r)*164 + k];
            #pragma unroll
            for (int kk = 0; kk < 4; kk++){
                float4 wq = __ldg(&Wq4[(k+kk)*32 + L]);
                float  wp = __ldg(&wp_ws_w[(k+kk)*32 + L]);
                unsigned long long wq01 = pk(wq.x, wq.y);
                unsigned long long wq23 = pk(wq.z, wq.w);
                unsigned long long wpp  = pk(wp, wp);
                float xv[4];
                #pragma unroll
                for (int r = 0; r < 4; r++)
                    xv[r] = (kk==0)?xr[r].x:(kk==1)?xr[r].y:(kk==2)?xr[r].z:xr[r].w;
                #pragma unroll
                for (int r = 0; r < 4; r++){
                    unsigned long long xx = pk(xv[r], xv[r]);
                    fma2(a01[r], xx, wq01);
                    fma2(a23[r], xx, wq23);
                }
                fma2(p01, pk(xv[0], xv[1]), wpp);
                fma2(p23, pk(xv[2], xv[3]), wpp);
            }
        }
        #pragma unroll
        for (int k = 128; k < 144; k++){
            float4 wq = __ldg(&Wq4[k*32 + L]);
            float  wp = __ldg(&wp_ws_w[k*32 + L]);
            unsigned long long wq01 = pk(wq.x, wq.y);
            unsigned long long wq23 = pk(wq.z, wq.w);
            unsigned long long wpp  = pk(wp, wp);
            float xq[4], xp[4];
            #pragma unroll
            for (int r = 0; r < 4; r++){
                xq[r] = sh_x[(r0+r)*164 + k];        // vn_q
                xp[r] = sh_x[(r0+r)*164 + 16 + k];   // vn_p
            }
            #pragma unroll
            for (int r = 0; r < 4; r++){
                unsigned long long xx = pk(xq[r], xq[r]);
                fma2(a01[r], xx, wq01);
                fma2(a23[r], xx, wq23);
            }
            fma2(p01, pk(xp[0], xp[1]), wpp);
            fma2(p23, pk(xp[2], xp[3]), wpp);
        }
        float4 bq  = __ldg(&((const float4*)q_ws_b)[L]);
        float4 wsq = __ldg(&((const float4*)attn_ws_w)[L & 7]);  // ws_q[4*(L&7) ..]
        float  bp  = __ldg(&wp_ws_b[L]);
        float2 pp01 = unpk(p01), pp23 = unpk(p23);
        float accp[4] = { pp01.x, pp01.y, pp23.x, pp23.y };
        #pragma unroll
        for (int r = 0; r < 4; r++){
            const int p = pr0 + r0 + r;
            float2 s01 = unpk(a01[r]), s23 = unpk(a23[r]);
            float so0 = s01.x+bq.x, so1 = s01.y+bq.y;
            float so2 = s23.x+bq.z, so3 = s23.y+bq.w;
            float sg0 = sigm(so0), sg1 = sigm(so1), sg2 = sigm(so2), sg3 = sigm(so3);
            *(float4*)&sh_x[(r0+r)*164 + 4*L] = make_float4(sg0, sg1, sg2, sg3);
            float pe = so0*sg0*wsq.x + so1*sg1*wsq.y + so2*sg2*wsq.z + so3*sg3*wsq.w;
            pe += __shfl_down_sync(0xffffffffu, pe, 4, 8);
            pe += __shfl_down_sync(0xffffffffu, pe, 2, 8);
            pe += __shfl_down_sync(0xffffffffu, pe, 1, 8);
            if ((L & 7) == 0) g_eq[(size_t)p*4 + (L >> 3)] = pe;
            g_e[(size_t)p*32 + L] = __expf(accp[r] + bp);
        }
    }
    __syncthreads();

    // ---- phase C1: gate GEMV (x shared across both i's, 2 partials each), vo -> qv
    {
        const int row = tid >> 3, g = tid & 7;
        const int i0 = g*2, i1 = i0 + 1;
        float a0 = sh_wsvb[i0], b0 = sh_wsvb[i1];
        float a1 = 0.f, b1 = 0.f, a2 = 0.f, b2 = 0.f, a3 = 0.f, b3 = 0.f;
        const float* xr = sh_x + row*164;
        #pragma unroll 8
        for (int j = 0; j < 128; j += 4){
            float x0 = xr[j], x1 = xr[j+1], x2 = xr[j+2], x3 = xr[j+3];
            a0 = fmaf(x0, sh_wsv[(j  )*16 + i0], a0);
            b0 = fmaf(x0, sh_wsv[(j  )*16 + i1], b0);
            a1 = fmaf(x1, sh_wsv[(j+1)*16 + i0], a1);
            b1 = fmaf(x1, sh_wsv[(j+1)*16 + i1], b1);
            a2 = fmaf(x2, sh_wsv[(j+2)*16 + i0], a2);
            b2 = fmaf(x2, sh_wsv[(j+2)*16 + i1], b2);
            a3 = fmaf(x3, sh_wsv[(j+3)*16 + i0], a3);
            b3 = fmaf(x3, sh_wsv[(j+3)*16 + i1], b3);
        }
        float gate0 = sigm((a0+a1)+(a2+a3));
        float gate1 = sigm((b0+b1)+(b2+b3));
        float qvv[2][3];
        #pragma unroll
        for (int d = 0; d < 3; d++){
            float v0 = 0.f, v1 = 0.f;
            #pragma unroll
            for (int k = 0; k < 16; k++){
                float vh = sh_vh[row*49 + d*16 + k];
                v0 = fmaf(vh, sh_wv[k*16 + i0], v0);
                v1 = fmaf(vh, sh_wv[k*16 + i1], v1);
            }
            qvv[0][d] = v0 * gate0;
            qvv[1][d] = v1 * gate1;
        }
        __syncthreads();
        #pragma unroll
        for (int ii = 0; ii < 2; ii++)
            #pragma unroll
            for (int d = 0; d < 3; d++)
                sh_v[row*49 + (i0+ii)*3 + d] = qvv[ii][d];
    }
    __syncthreads();

    // ---- phase C2: qh[h][d][j], thread handles j = g
    {
        const int row = tid >> 3, g = tid & 7;
        const int p = pr0 + row;
        #pragma unroll
        for (int h = 0; h < 4; h++)
            #pragma unroll
            for (int d = 0; d < 3; d++){
                float acc = 0.f;
                #pragma unroll
                for (int m = 0; m < 4; m++)
                    acc = fmaf(sh_v[row*49 + (h*4+m)*3 + d], sh_whq[m*8 + g], acc);
                g_qh[(size_t)p*96 + h*24 + d*8 + g] = acc;
            }
    }
}

// ---------------- K2: pooled softmax reduction ----------------
__global__ __launch_bounds__(256) void k_pool(
    const float* __restrict__ s, const float* __restrict__ v)
{
    __shared__ float sh_e[8][32];
    __shared__ float sh_x[8][176];
    const int tid = threadIdx.x, lane = tid & 31, w = tid >> 5;
    const int c  = blockIdx.x & 1;
    const int bi = blockIdx.x >> 1;
    const int nstride = (gridDim.x >> 1) * 8;

    float acc[22];
    #pragma unroll
    for (int j = 0; j < 22; j++) acc[j] = 0.f;
    float z = 0.f;

    for (int n0 = bi*8; n0 < N_; n0 += nstride){
        for (int q = tid; q < 8*208; q += 256){
            int rr = q / 208, off = q - rr*208;
            int n = n0 + rr;
            if (off < 32){
                sh_e[rr][off] = (n < N_) ? g_e[((size_t)(n*2+c))*32 + off] : 0.f;
            } else if (n < N_){
                if (off < 160) sh_x[rr][off-32]  = s[((size_t)(n*2+c))*128 + off - 32];
                else           sh_x[rr][off-32]  = v[((size_t)(n*2+c))*48  + off - 160];
            }
        }
        __syncthreads();
        #pragma unroll
        for (int rr = 0; rr < 8; rr++){
            float e = sh_e[rr][lane];
            #pragma unroll
            for (int j = 0; j < 22; j++)
                acc[j] = fmaf(e, sh_x[rr][w*22 + j], acc[j]);
            if (w == 0) z += e;
        }
        __syncthreads();
    }
    float* dst = g_num + (size_t)(c*32 + lane)*176 + w*22;
    #pragma unroll
    for (int j = 0; j < 22; j++) atomicAdd(dst + j, acc[j]);
    if (w == 0) atomicAdd(&g_Z[c*32 + lane], z);
}

// ---------------- K3: k & vv GVPs on 64 pooled rows ----------------
// grid (32, 2, 2): r, c, branch (0=k, 1=v). 128 threads. 4-way ILP on all GEMVs.
__global__ __launch_bounds__(128) void k_small(
    const float* __restrict__ k_wh, const float* __restrict__ k_ws_w, const float* __restrict__ k_ws_b,
    const float* __restrict__ k_wv, const float* __restrict__ k_wsv_w, const float* __restrict__ k_wsv_b,
    const float* __restrict__ v_wh, const float* __restrict__ v_ws_w, const float* __restrict__ v_ws_b,
    const float* __restrict__ v_wv, const float* __restrict__ v_wsv_w, const float* __restrict__ v_wsv_b,
    const float* __restrict__ attn_wh, const float* __restrict__ attn_ws_w)
{
    __shared__ float sh_s[128], sh_vg[48];
    __shared__ float sh_vh[48], sh_vn[16];
    __shared__ float sh_g[128], sh_kv[48];
    const int r = blockIdx.x, c = blockIdx.y, rc = r*2 + c;
    const int isv = blockIdx.z;
    const int t = threadIdx.x;

    const float* wh   = isv ? v_wh    : k_wh;
    const float* Wsw  = isv ? v_ws_w  : k_ws_w;
    const float* Wsb  = isv ? v_ws_b  : k_ws_b;
    const float* Wv   = isv ? v_wv    : k_wv;
    const float* Wsvw = isv ? v_wsv_w : k_wsv_w;
    const float* Wsvb = isv ? v_wsv_b : k_wsv_b;

    float invZ = 1.f / g_Z[c*32 + r];
    sh_s[t] = g_num[(c*32 + r)*176 + t] * invZ;
    if (t < 48) sh_vg[t] = g_num[(c*32 + r)*176 + 128 + t] * invZ;
    __syncthreads();

    if (t < 16){
        float a0=0,a1=0,a2=0;
        #pragma unroll
        for (int kk = 0; kk < 16; kk++){
            float w_ = __ldg(wh + kk*16 + t);
            a0 = fmaf(sh_vg[kk*3+0], w_, a0);
            a1 = fmaf(sh_vg[kk*3+1], w_, a1);
            a2 = fmaf(sh_vg[kk*3+2], w_, a2);
        }
        sh_vh[t] = a0; sh_vh[16+t] = a1; sh_vh[32+t] = a2;
        sh_vn[t] = sqrtf(fmaxf(a0*a0+a1*a1+a2*a2, EPSc));
    }
    __syncthreads();

    {   // so GEMV, col t, 4 independent partials over m-quarters
        float a0 = __ldg(Wsb + t), a1 = 0.f, a2 = 0.f, a3 = 0.f;
        #pragma unroll 8
        for (int m = 0; m < 32; m++){
            a0 = fmaf(sh_s[m],    __ldg(Wsw + (m    )*128 + t), a0);
            a1 = fmaf(sh_s[m+32], __ldg(Wsw + (m+32 )*128 + t), a1);
            a2 = fmaf(sh_s[m+64], __ldg(Wsw + (m+64 )*128 + t), a2);
            a3 = fmaf(sh_s[m+96], __ldg(Wsw + (m+96 )*128 + t), a3);
        }
        #pragma unroll
        for (int m = 0; m < 16; m += 4){
            a0 = fmaf(sh_vn[m],   __ldg(Wsw + (128+m  )*128 + t), a0);
            a1 = fmaf(sh_vn[m+1], __ldg(Wsw + (128+m+1)*128 + t), a1);
            a2 = fmaf(sh_vn[m+2], __ldg(Wsw + (128+m+2)*128 + t), a2);
            a3 = fmaf(sh_vn[m+3], __ldg(Wsw + (128+m+3)*128 + t), a3);
        }
        float acc = (a0+a1)+(a2+a3);
        float g = sigm(acc);
        sh_g[t] = g;
        if (isv){
            g_vs[rc*128 + t] = acc * g;              // silu(so_v)
        } else {
            float part = (acc*g) * __ldg(attn_ws_w + 32 + (t & 31));
            #pragma unroll
            for (int off = 16; off; off >>= 1) part += __shfl_down_sync(0xffffffffu, part, off);
            if ((t & 31) == 0) g_ek[rc*4 + (t >> 5)] = part;
        }
    }
    __syncthreads();

    if (t < 16){
        float a0 = __ldg(Wsvb + t), a1 = 0.f, a2 = 0.f, a3 = 0.f;
        #pragma unroll 8
        for (int j = 0; j < 32; j++){
            a0 = fmaf(sh_g[j],    __ldg(Wsvw + (j   )*16 + t), a0);
            a1 = fmaf(sh_g[j+32], __ldg(Wsvw + (j+32)*16 + t), a1);
            a2 = fmaf(sh_g[j+64], __ldg(Wsvw + (j+64)*16 + t), a2);
            a3 = fmaf(sh_g[j+96], __ldg(Wsvw + (j+96)*16 + t), a3);
        }
        float gate = sigm((a0+a1)+(a2+a3));
        #pragma unroll
        for (int d = 0; d < 3; d++){
            float vo = 0.f;
            #pragma unroll
            for (int kk = 0; kk < 16; kk++)
                vo = fmaf(sh_vh[d*16 + kk], __ldg(Wv + kk*16 + t), vo);
            if (isv) g_vv[rc*48 + t*3 + d] = vo * gate;   // layout == h*12 + dv*3 + d
            else     sh_kv[t*3 + d] = vo * gate;
        }
    }
    __syncthreads();

    if (!isv && t < 8){
        #pragma unroll
        for (int h = 0; h < 4; h++)
            #pragma unroll
            for (int d = 0; d < 3; d++){
                float acc = 0.f;
                #pragma unroll
                for (int m = 0; m < 4; m++)
                    acc = fmaf(sh_kv[(h*4+m)*3 + d], __ldg(attn_wh + (4+m)*8 + t), acc);
                g_kh[rc*96 + h*24 + d*8 + t] = acc;
            }
    }
}

// ---------------- K4: attention ----------------
// grid (250, 2): blockIdx.y = c. Warp: fixed h = w&3; processes groups of 4 n.
__global__ __launch_bounds__(256) void k_attn(
    const float* __restrict__ attn_ws_w, const float* __restrict__ attn_ws_b,
    float* __restrict__ out_s, float* __restrict__ out_v)
{
    __shared__ float kh_s[32*96];
    __shared__ float vs_s[32*128];
    __shared__ float vv_s[32*48];
    __shared__ float ek_s[128];
    const int c = blockIdx.y, tid = threadIdx.x, lane = tid & 31, w = tid >> 5;

    for (int idx = tid; idx < 3072; idx += 256){ int r = idx/96;  kh_s[idx] = g_kh[(r*2+c)*96  + idx - r*96 ]; }
    for (int idx = tid; idx < 4096; idx += 256){ int r = idx>>7;  vs_s[idx] = g_vs[(r*2+c)*128 + (idx & 127)]; }
    for (int idx = tid; idx < 1536; idx += 256){ int r = idx/48;  vv_s[idx] = g_vv[(r*2+c)*48  + idx - r*48 ]; }
    if (tid < 128) ek_s[tid] = g_ek[((tid>>2)*2 + c)*4 + (tid & 3)];
    __syncthreads();

    const int h = w & 3, g2 = w >> 2;

    float kh[24];
    {
        const float4* k4 = (const float4*)(kh_s + lane*96 + h*24);
        #pragma unroll
        for (int j = 0; j < 6; j++){
            float4 t4 = k4[j];
            kh[j*4] = t4.x; kh[j*4+1] = t4.y; kh[j*4+2] = t4.z; kh[j*4+3] = t4.w;
        }
    }
    float wn[8];
    #pragma unroll
    for (int j = 0; j < 8; j++) wn[j] = __ldg(attn_ws_w + 64 + j);
    const float ekb = ek_s[lane*4 + h] + __ldg(attn_ws_b);
    const float sc = 0.17677669529663687f;   // 1/sqrt(32)
    const int   jv = (lane < 12) ? lane : 0;
    const float* vsb = vs_s + h*32 + lane;
    const float* vvb = vv_s + h*12 + jv;

    for (int grp = blockIdx.x*2 + g2; grp < 2500; grp += gridDim.x*2){
        const int nbase = grp * 4;
        float alpha[4];
        #pragma unroll
        for (int t4 = 0; t4 < 4; t4++){
            const int p = (nbase + t4)*2 + c;
            float q[24];
            const float4* qp = (const float4*)(g_qh + (size_t)p*96 + h*24);
            #pragma unroll
            for (int j = 0; j < 6; j++){
                float4 v4 = __ldg(&qp[j]);
                q[j*4] = v4.x; q[j*4+1] = v4.y; q[j*4+2] = v4.z; q[j*4+3] = v4.w;
            }
            float e = __ldg(&g_eq[(size_t)p*4 + h]) + ekb;
            #pragma unroll
            for (int j = 0; j < 8; j++){
                float s0 = q[j]    + kh[j];
                float s1 = q[8+j]  + kh[8+j];
                float s2 = q[16+j] + kh[16+j];
                float ss = fmaf(s0,s0, fmaf(s1,s1, s2*s2));
                e = fmaf(sqrtf(fmaxf(ss, EPSc)), wn[j], e);
            }
            e *= sc;
            float m = e;
            #pragma unroll
            for (int off = 16; off; off >>= 1) m = fmaxf(m, __shfl_xor_sync(0xffffffffu, m, off));
            float ex = __expf(e - m);
            float z = ex;
            #pragma unroll
            for (int off = 16; off; off >>= 1) z += __shfl_xor_sync(0xffffffffu, z, off);
            alpha[t4] = ex / z;
        }

        float accs[4] = {0,0,0,0}, accv[4] = {0,0,0,0};
        #pragma unroll
        for (int r2 = 0; r2 < 32; r2++){
            float vsv = vsb[r2*128];
            float vvv = vvb[r2*48];
            #pragma unroll
            for (int t4 = 0; t4 < 4; t4++){
                float a = __shfl_sync(0xffffffffu, alpha[t4], r2);
                accs[t4] = fmaf(a, vsv, accs[t4]);
                accv[t4] = fmaf(a, vvv, accv[t4]);
            }
        }
        #pragma unroll
        for (int t4 = 0; t4 < 4; t4++){
            const int p = (nbase + t4)*2 + c;
            out_s[(size_t)p*128 + h*32 + lane] = accs[t4];
            if (lane < 12) out_v[(size_t)p*48 + h*12 + lane] = accv[t4];
        }
    }
}

// ---------------- launch ----------------
extern "C" void kernel_launch(void* const* d_in, const int* in_sizes, int n_in,
                              void* d_out, int out_size)
{
    const float* s        = (const float*)d_in[0];
    const float* v        = (const float*)d_in[1];
    const float* wp_wh    = (const float*)d_in[2];
    const float* wp_ws_w  = (const float*)d_in[3];
    const float* wp_ws_b  = (const float*)d_in[4];
    const float* q_wh     = (const float*)d_in[5];
    const float* q_ws_w   = (const float*)d_in[6];
    const float* q_ws_b   = (const float*)d_in[7];
    const float* q_wv     = (const float*)d_in[8];
    const float* q_wsv_w  = (const float*)d_in[9];
    const float* q_wsv_b  = (const float*)d_in[10];
    const float* k_wh     = (const float*)d_in[11];
    const float* k_ws_w   = (const float*)d_in[12];
    const float* k_ws_b   = (const float*)d_in[13];
    const float* k_wv     = (const float*)d_in[14];
    const float* k_wsv_w  = (const float*)d_in[15];
    const float* k_wsv_b  = (const float*)d_in[16];
    const float* vv_wh    = (const float*)d_in[17];
    const float* vv_ws_w  = (const float*)d_in[18];
    const float* vv_ws_b  = (const float*)d_in[19];
    const float* vv_wv    = (const float*)d_in[20];
    const float* vv_wsv_w = (const float*)d_in[21];
    const float* vv_wsv_b = (const float*)d_in[22];
    const float* attn_wh  = (const float*)d_in[23];
    const float* attn_ws_w= (const float*)d_in[24];
    const float* attn_ws_b= (const float*)d_in[25];

    float* out_s = (float*)d_out;
    float* out_v = out_s + (size_t)P_*128;   // out_s (N,C,128) then out_v (N,C,16,3)

    k_init <<<12, 256>>>();
    k_main <<<625, 256>>>(s, v, wp_wh, wp_ws_w, wp_ws_b,
                          q_wh, q_ws_w, q_ws_b, q_wv, q_wsv_w, q_wsv_b,
                          attn_wh, attn_ws_w);
    k_pool <<<264, 256>>>(s, v);
    k_small<<<dim3(32,2,2), 128>>>(k_wh, k_ws_w, k_ws_b, k_wv, k_wsv_w, k_wsv_b,
                                   vv_wh, vv_ws_w, vv_ws_b, vv_wv, vv_wsv_w, vv_wsv_b,
                                   attn_wh, attn_ws_w);
    k_attn <<<dim3(250,2), 256>>>(attn_ws_w, attn_ws_b, out_s, out_v);
}